// round 15
// baseline (speedup 1.0000x reference)
#include <cuda_runtime.h>
#include <cstdint>

#define BIGV 1e10f
#define TT 1024
#define BB 32
#define DD 64
#define NDIAG 2047   // row+col in [0, 2046]

// Diagonal-major cost scratch: g_cost[b][d][row], d = row+col.
static __device__ float g_cost[(size_t)BB * NDIAG * TT];

// ---------------------------------------------------------------------------
// Kernel A: cost matrix. 64x64 tiles, 4x4 reg tiling. Stride 68 (16B-aligned
// rows) so the GEMM inner loop is 2x LDS.128 per k (broadcast + contiguous)
// instead of 8 scalar LDS -> removes the 89.9% L1 bottleneck.
// ---------------------------------------------------------------------------
#define STR 68
__global__ __launch_bounds__(256) void cost_kernel(const float* __restrict__ x,
                                                   const float* __restrict__ y) {
    const int bz = blockIdx.z;
    const int br = blockIdx.y;
    const int bc = blockIdx.x;
    const int tid = threadIdx.x;

    __shared__ __align__(16) float arena[2 * 64 * STR];   // 34.8 KB
    __shared__ float x2s[64], y2s[64];
    float* xsT = arena;                 // xsT[k*STR + r]
    float* ysT = arena + 64 * STR;      // ysT[k*STR + c]
    float (*res)[72] = (float (*)[72])arena;   // aliases arena after compute

    const float* xb = x + ((size_t)bz * TT + br * 64) * DD;
    const float* yb = y + ((size_t)bz * TT + bc * 64) * DD;

    #pragma unroll
    for (int i = 0; i < 16; i++) {
        int idx = tid + i * 256;
        int r = idx >> 6;
        int d = idx & 63;
        xsT[d * STR + r] = xb[r * DD + d];
        ysT[d * STR + r] = yb[r * DD + d];
    }
    __syncthreads();

    if (tid < 64) {
        float s = 0.f;
        #pragma unroll
        for (int k = 0; k < 64; k++) { float v = xsT[k * STR + tid]; s = fmaf(v, v, s); }
        x2s[tid] = s;
    } else if (tid < 128) {
        int c = tid - 64;
        float s = 0.f;
        #pragma unroll
        for (int k = 0; k < 64; k++) { float v = ysT[k * STR + c]; s = fmaf(v, v, s); }
        y2s[c] = s;
    }

    const int tx = tid & 15;
    const int ty = tid >> 4;
    float acc[4][4] = {};
    #pragma unroll
    for (int k = 0; k < 64; k++) {
        float4 xv = *(const float4*)(xsT + k * STR + ty * 4);   // broadcast LDS.128
        float4 yv = *(const float4*)(ysT + k * STR + tx * 4);   // contiguous LDS.128
        float xr[4] = {xv.x, xv.y, xv.z, xv.w};
        float yc[4] = {yv.x, yv.y, yv.z, yv.w};
        #pragma unroll
        for (int r = 0; r < 4; r++)
            #pragma unroll
            for (int c = 0; c < 4; c++)
                acc[r][c] = fmaf(xr[r], yc[c], acc[r][c]);
    }
    __syncthreads();

    float xr2[4], yc2[4];
    #pragma unroll
    for (int r = 0; r < 4; r++) xr2[r] = x2s[ty * 4 + r];
    #pragma unroll
    for (int c = 0; c < 4; c++) yc2[c] = y2s[tx * 4 + c];
    #pragma unroll
    for (int r = 0; r < 4; r++)
        #pragma unroll
        for (int c = 0; c < 4; c++)
            res[ty * 4 + r][tx * 4 + c] =
                fmaxf(xr2[r] + yc2[c] - 2.0f * acc[r][c], 0.0f);
    __syncthreads();

    const int wid = tid >> 5, lane = tid & 31;
    const int dbase = br * 64 + bc * 64;
    for (int dl = wid; dl < 127; dl += 8) {
        int rlo = dl > 63 ? dl - 63 : 0;
        int rhi = dl < 63 ? dl : 63;
        size_t gbase = ((size_t)bz * NDIAG + (dbase + dl)) * TT + (size_t)br * 64;
        for (int r0 = rlo; r0 <= rhi; r0 += 32) {
            int r = r0 + lane;
            if (r <= rhi) g_cost[gbase + r] = res[r][dl - r];
        }
    }
}

// ---------------------- helpers ----------------------------
__device__ __forceinline__ uint32_t smem_u32(const void* p) {
    uint32_t a;
    asm("{ .reg .u64 t; cvta.to.shared.u64 t, %1; cvt.u32.u64 %0, t; }"
        : "=r"(a) : "l"(p));
    return a;
}
__device__ __forceinline__ uint32_t mapa_rank(uint32_t a, uint32_t rank) {
    uint32_t r;
    asm("mapa.shared::cluster.u32 %0, %1, %2;" : "=r"(r) : "r"(a), "r"(rank));
    return r;
}
__device__ __forceinline__ void st_remote_f32(uint32_t a, float v) {
    asm volatile("st.shared::cluster.f32 [%0], %1;" :: "r"(a), "f"(v) : "memory");
}
__device__ __forceinline__ float4 ldsv4(uint32_t a) {
    float4 v;
    asm volatile("ld.volatile.shared.v4.f32 {%0, %1, %2, %3}, [%4];"
                 : "=f"(v.x), "=f"(v.y), "=f"(v.z), "=f"(v.w) : "r"(a));
    return v;
}
__device__ __forceinline__ void cluster_sync_all() {
    asm volatile("barrier.cluster.arrive.aligned;" ::: "memory");
    asm volatile("barrier.cluster.wait.aligned;" ::: "memory");
}
__device__ __forceinline__ float softmin3(float a, float bb, float c) {
    float mnab = fminf(a, bb);
    float mxab = fmaxf(a, bb);
    float mn   = fminf(mnab, c);
    float hi   = fmaxf(mxab, c);
    float mid  = fmaxf(mnab, fminf(mxab, c));
    float sum  = 1.0f + __expf(mn - mid) + __expf(mn - hi);
    return mn - __logf(sum);
}

// ---------------------------------------------------------------------------
// Kernel B: FENCE-FREE sentinel-halo pipelined DP.
// 64 CTAs (2-CTA clusters = 1 batch), 256 threads (8 warps = 2/SMSP),
// 2 rows/thread. All halo slots initialized to qNaN; DP values are never NaN
// and each slot is written exactly once, so a non-NaN word IS its own ready
// flag: no fences, no counters, no barriers, no ordering needed. Producers
// never stall (plain STS intra; fire-and-forget st.shared::cluster inter).
// Consumers volatile-poll 8 words per segment (~0 cyc in steady state).
// Branch-free inner loop from R13 kept.
// ---------------------------------------------------------------------------
#define SEG 8
#define NSEG 256                      // SEG*NSEG = 2048 >= 2047 diagonals
#define DPSMEM (8 * 2048 * 4)         // 7 intra halos + 1 incoming = 64 KB

__global__ void __cluster_dims__(2, 1, 1) __launch_bounds__(256)
dp_kernel(float* __restrict__ out) {
    extern __shared__ float halo_sm[];   // [7][2048] intra + [2048] halo_in

    const int cta = blockIdx.x;       // 0..63
    const int b = cta >> 1;           // batch
    const int q = cta & 1;            // cluster rank
    const int t = threadIdx.x;        // 0..255
    const int lane = t & 31;
    const int w = t >> 5;             // warp 0..7
    const int W = q * 8 + w;          // global 64-row band 0..15
    const int r0 = W * 64 + lane * 2; // owned rows r0, r0+1

    // ---- init all halo slots to sentinel (qNaN), then cluster sync ----
    const float SENT = __int_as_float(0x7fc00000);
    {
        float4 s4 = make_float4(SENT, SENT, SENT, SENT);
        float4* p = (float4*)halo_sm;
        #pragma unroll
        for (int i = 0; i < 16; i++) p[t + i * 256] = s4;   // 4096 float4s
    }
    __syncthreads();
    cluster_sync_all();   // peer's sentinel init done before any remote store

    float* halo_in = halo_sm + 7 * 2048;
    float* myhalo = halo_sm + w * 2048;                    // valid for w<7
    const float* lhalo = (w == 0) ? halo_in : halo_sm + (w - 1) * 2048;

    uint32_t rem_halo = 0;
    if (q == 0) rem_halo = mapa_rank(smem_u32(halo_in), 1u);
    const bool bnd_produce = (w == 7) && (q == 0);

    float v1_0 = BIGV, v1_1 = BIGV;   // d_{k-1}[r0+1], d_{k-1}[r0+2]
    float v2_0 = BIGV, v2_1 = BIGV;   // d_{k-2}[...]
    float L1 = BIGV;                  // d_{k-1}[r0]
    float L2 = (W == 0 && lane == 0) ? 0.0f : BIGV;   // d0[0] = 0

    const float* costbase = g_cost + (size_t)b * NDIAG * TT + r0;
    const int kminA = r0 + 2;
    const int kmaxA = r0 + 2 + TT;

    // band-level windows (uniform across warp)
    const int W0 = 64 * W + 2;
    const int W1 = 64 * W + 64 + TT;
    const int F0 = 64 * W + 65;
    const int F1 = 64 * W + 1 + TT;
    const int P0 = 64 * W + 64;
    const int P1 = 64 * W + 2 + TT;

    float res = BIGV;
    float2 cbuf[SEG], nbuf[SEG];
    float hb[SEG];
    #pragma unroll
    for (int j = 0; j < SEG; j++) hb[j] = BIGV;   // W==0 keeps BIGV (d_k[0]=BIG)

    // preload segment 0 costs (masked)
    #pragma unroll
    for (int j = 0; j < SEG; j++) {
        int k = 2 + j;
        cbuf[j] = make_float2(0.f, 0.f);
        if ((k >= kminA) & (k <= kmaxA))
            cbuf[j] = *(const float2*)(costbase + (size_t)(k - 2) * TT);
    }

    int k0 = 2;
    for (int s = 0; s < NSEG; s++) {
        const bool active = (k0 <= W1) & (k0 + SEG - 1 >= W0);

        // ---- gate: poll this segment's 8 halo words until non-NaN ----
        if (active && (W > 0)) {
            uint32_t a0 = smem_u32(&lhalo[k0 - 2]);   // (k0-2)=8s -> 16B aligned
            float4 h0 = ldsv4(a0);
            float4 h1 = ldsv4(a0 + 16);
            while ((h0.x != h0.x) | (h0.y != h0.y) | (h0.z != h0.z) | (h0.w != h0.w) |
                   (h1.x != h1.x) | (h1.y != h1.y) | (h1.z != h1.z) | (h1.w != h1.w)) {
                __nanosleep(20);
                h0 = ldsv4(a0);
                h1 = ldsv4(a0 + 16);
            }
            hb[0] = h0.x; hb[1] = h0.y; hb[2] = h0.z; hb[3] = h0.w;
            hb[4] = h1.x; hb[5] = h1.y; hb[6] = h1.z; hb[7] = h1.w;
        }

        // ---- prefetch next segment costs ----
        const int k0n = k0 + SEG;
        if ((k0n <= W1) & (k0n + SEG - 1 >= W0) & (s + 1 < NSEG)) {
            const float* p = costbase + (size_t)(k0n - 2) * TT;
            if ((k0n >= P0) & (k0n + SEG - 1 <= P1)) {
                #pragma unroll
                for (int j = 0; j < SEG; j++)
                    nbuf[j] = *(const float2*)(p + (size_t)j * TT);
            } else {
                #pragma unroll
                for (int j = 0; j < SEG; j++) {
                    int k = k0n + j;
                    nbuf[j] = make_float2(0.f, 0.f);
                    if ((k >= kminA) & (k <= kmaxA))
                        nbuf[j] = *(const float2*)(p + (size_t)j * TT);
                }
            }
        }

        // ---- compute segment (branch-free inner loops) ----
        float sh[SEG];
        if (!active) {
            #pragma unroll
            for (int j = 0; j < SEG; j++) sh[j] = BIGV;
        } else if ((k0 >= F0) & (k0 + SEG - 1 <= F1)) {
            // interior fast path
            #pragma unroll
            for (int j = 0; j < SEG; j++) {
                float cur1 = cbuf[j].y + softmin3(v2_0, v1_0, v1_1);
                float cur0 = cbuf[j].x + softmin3(L2, L1, v1_0);
                float nb = __shfl_up_sync(0xffffffffu, cur1, 1);
                nb = (lane == 0) ? hb[j] : nb;
                sh[j] = cur1;
                L2 = L1; L1 = nb;
                v2_0 = v1_0; v2_1 = v1_1;
                v1_0 = cur0; v1_1 = cur1;
                res = cur1;
            }
        } else {
            // edge path (masked with selects)
            #pragma unroll
            for (int j = 0; j < SEG; j++) {
                const int k = k0 + j;
                const int rlo = k - 1 - TT;
                const int rhi = k - 2;
                const bool tv = (k >= kminA) & (k <= kmaxA);

                float sm1 = softmin3(v2_0, v1_0, v1_1);
                float sm0 = softmin3(L2, L1, v1_0);
                int r1 = r0 + 1;
                float cur1 = (tv & (r1 >= rlo) & (r1 <= rhi)) ? cbuf[j].y + sm1 : BIGV;
                float cur0 = (tv & (r0 >= rlo) & (r0 <= rhi)) ? cbuf[j].x + sm0 : BIGV;
                res = tv ? cur1 : res;

                float nb = __shfl_up_sync(0xffffffffu, cur1, 1);
                nb = (lane == 0) ? hb[j] : nb;
                sh[j] = cur1;
                L2 = L1; L1 = nb;
                v2_0 = v1_0; v2_1 = v1_1;
                v1_0 = cur0; v1_1 = cur1;
            }
        }

        // ---- epilogue: publish halo (no fences; words self-validate) ----
        if (lane == 31) {
            if (w < 7) {
                *(float4*)&myhalo[k0 - 2] = make_float4(sh[0], sh[1], sh[2], sh[3]);
                *(float4*)&myhalo[k0 + 2] = make_float4(sh[4], sh[5], sh[6], sh[7]);
            } else if (bnd_produce) {
                #pragma unroll
                for (int j = 0; j < SEG; j++)
                    st_remote_f32(rem_halo + (uint32_t)(k0 - 2 + j) * 4u, sh[j]);
            }
        }

        #pragma unroll
        for (int j = 0; j < SEG; j++) cbuf[j] = nbuf[j];
        k0 = k0n;
    }

    // answer = d_{2T}[T]: row 1023 -> q=1, warp 7, lane 31, second row (k=2048)
    if (q == 1 && t == 255) out[b] = res;
}

extern "C" void kernel_launch(void* const* d_in, const int* in_sizes, int n_in,
                              void* d_out, int out_size) {
    const float* x = (const float*)d_in[0];
    const float* y = (const float*)d_in[1];
    float* out = (float*)d_out;

    cudaFuncSetAttribute(dp_kernel,
                         cudaFuncAttributeMaxDynamicSharedMemorySize, DPSMEM);

    dim3 gridA(TT / 64, TT / 64, BB);   // (16, 16, 32)
    cost_kernel<<<gridA, 256>>>(x, y);
    dp_kernel<<<BB * 2, 256, DPSMEM>>>(out);
}

// round 16
// speedup vs baseline: 1.4404x; 1.4404x over previous
#include <cuda_runtime.h>
#include <cstdint>

#define BIGV 1e10f
#define TT 1024
#define BB 32
#define DD 64
#define NDIAG 2047   // row+col in [0, 2046]

// Diagonal-major cost scratch: g_cost[b][d][row], d = row+col.
static __device__ float g_cost[(size_t)BB * NDIAG * TT];

// ---------------------------------------------------------------------------
// Kernel A: cost matrix, 64x64 tiles, 4x4 reg tiling, XOR-swizzled smem.
// Layout: tile row k (the D dim), 16 granules of 4 floats; granule g stored
// at g ^ (k & 15). GEMM loads are LDS.128, conflict-free (y: 16 distinct
// granules spanning the 256B row; x: broadcast). Transpose store is 2-way
// conflicted (once per tile, cheap). Writes anti-diagonal-major to g_cost.
// ---------------------------------------------------------------------------
__global__ __launch_bounds__(256) void cost_kernel(const float* __restrict__ x,
                                                   const float* __restrict__ y) {
    const int bz = blockIdx.z;
    const int br = blockIdx.y;
    const int bc = blockIdx.x;
    const int tid = threadIdx.x;

    __shared__ __align__(16) float arena[2 * 64 * 64];   // 32 KB
    __shared__ float x2s[64], y2s[64];
    float* xsT = arena;               // swizzled [k][r]
    float* ysT = arena + 64 * 64;     // swizzled [k][c]
    float (*res)[72] = (float (*)[72])arena;   // aliases arena after compute

    const float* xb = x + ((size_t)bz * TT + br * 64) * DD;
    const float* yb = y + ((size_t)bz * TT + bc * 64) * DD;

    // Transpose loads with granule swizzle: element (row r, dim d) goes to
    // float index d*64 + ((r>>2)^(d&15))*4 + (r&3).
    #pragma unroll
    for (int i = 0; i < 16; i++) {
        int idx = tid + i * 256;   // 0..4095
        int r = idx >> 6;
        int d = idx & 63;
        int sw = d * 64 + ((((r >> 2) ^ d) & 15) << 2) + (r & 3);
        xsT[sw] = xb[r * DD + d];
        ysT[sw] = yb[r * DD + d];
    }
    __syncthreads();

    if (tid < 64) {
        float s = 0.f;
        #pragma unroll
        for (int k = 0; k < 64; k++) {
            float v = xsT[k * 64 + ((((tid >> 2) ^ k) & 15) << 2) + (tid & 3)];
            s = fmaf(v, v, s);
        }
        x2s[tid] = s;
    } else if (tid < 128) {
        int c = tid - 64;
        float s = 0.f;
        #pragma unroll
        for (int k = 0; k < 64; k++) {
            float v = ysT[k * 64 + ((((c >> 2) ^ k) & 15) << 2) + (c & 3)];
            s = fmaf(v, v, s);
        }
        y2s[c] = s;
    }

    const int tx = tid & 15;   // col granule
    const int ty = tid >> 4;   // row granule
    float acc[4][4] = {};
    #pragma unroll
    for (int k = 0; k < 64; k++) {
        float4 xv = *(const float4*)(xsT + k * 64 + (((ty ^ k) & 15) << 2));
        float4 yv = *(const float4*)(ysT + k * 64 + (((tx ^ k) & 15) << 2));
        float xr[4] = {xv.x, xv.y, xv.z, xv.w};
        float yc[4] = {yv.x, yv.y, yv.z, yv.w};
        #pragma unroll
        for (int r = 0; r < 4; r++)
            #pragma unroll
            for (int c = 0; c < 4; c++)
                acc[r][c] = fmaf(xr[r], yc[c], acc[r][c]);
    }
    __syncthreads();

    float xr2[4], yc2[4];
    #pragma unroll
    for (int r = 0; r < 4; r++) xr2[r] = x2s[ty * 4 + r];
    #pragma unroll
    for (int c = 0; c < 4; c++) yc2[c] = y2s[tx * 4 + c];
    #pragma unroll
    for (int r = 0; r < 4; r++)
        #pragma unroll
        for (int c = 0; c < 4; c++)
            res[ty * 4 + r][tx * 4 + c] =
                fmaxf(xr2[r] + yc2[c] - 2.0f * acc[r][c], 0.0f);
    __syncthreads();

    const int wid = tid >> 5, lane = tid & 31;
    const int dbase = br * 64 + bc * 64;
    for (int dl = wid; dl < 127; dl += 8) {
        int rlo = dl > 63 ? dl - 63 : 0;
        int rhi = dl < 63 ? dl : 63;
        size_t gbase = ((size_t)bz * NDIAG + (dbase + dl)) * TT + (size_t)br * 64;
        for (int r0 = rlo; r0 <= rhi; r0 += 32) {
            int r = r0 + lane;
            if (r <= rhi) g_cost[gbase + r] = res[r][dl - r];
        }
    }
}

__device__ __forceinline__ float softmin3(float a, float bb, float c) {
    float mnab = fminf(a, bb);
    float mxab = fmaxf(a, bb);
    float mn   = fminf(mnab, c);
    float hi   = fmaxf(mxab, c);
    float mid  = fmaxf(mnab, fminf(mxab, c));
    float sum  = 1.0f + __expf(mn - mid) + __expf(mn - hi);
    return mn - __logf(sum);
}

// ---------------------------------------------------------------------------
// Kernel B: EXACT round-13 DP (proven 281us). Elastic pipelined, branch-free
// memory-free inner loop, 32 CTAs (1/batch), 512 threads, 2 rows/thread,
// SEG=8, full-size per-warp halo arrays in 120KB dynamic smem, counter sync.
// ---------------------------------------------------------------------------
#define SEG 8
#define NSEG 256   // SEG*NSEG = 2048 >= 2047 diagonals (k = 2..2049)
#define HALO_BYTES (15 * 2048 * 4)

__global__ __launch_bounds__(512) void dp_kernel(float* __restrict__ out) {
    extern __shared__ float halo_sm[];   // [15][2048]
    __shared__ int prog[16];

    const int b = blockIdx.x;
    const int t = threadIdx.x;        // 0..511
    const int lane = t & 31;
    const int w = t >> 5;             // warp 0..15
    const int r0 = t << 1;            // owned rows r0, r0+1

    if (t < 16) prog[t] = 0;
    __syncthreads();
    volatile int* vprog = prog;

    float v1_0 = BIGV, v1_1 = BIGV;   // d_{k-1}[r0+1], d_{k-1}[r0+2]
    float v2_0 = BIGV, v2_1 = BIGV;   // d_{k-2}[...]
    float L1 = BIGV;                  // d_{k-1}[r0]
    float L2 = (t == 0) ? 0.0f : BIGV;

    const float* costbase = g_cost + (size_t)b * NDIAG * TT + r0;
    const int kminA = r0 + 2;
    const int kmaxA = r0 + 2 + TT;

    // warp-level windows (uniform across warp)
    const int W0 = 64 * w + 2;
    const int W1 = 64 * w + 64 + TT;
    const int F0 = 64 * w + 65;
    const int F1 = 64 * w + 1 + TT;
    const int P0 = 64 * w + 64;
    const int P1 = 64 * w + 2 + TT;

    float* myhalo = &halo_sm[w * 2048];            // valid only for w<15
    const float* lhalo = &halo_sm[(w - 1) * 2048]; // valid only for w>0

    float res = BIGV;
    float2 cbuf[SEG], nbuf[SEG];
    float hb[SEG];
    #pragma unroll
    for (int j = 0; j < SEG; j++) hb[j] = BIGV;  // w=0 keeps BIGV (d_k[0] = BIG)

    // preload segment 0 costs (masked)
    #pragma unroll
    for (int j = 0; j < SEG; j++) {
        int k = 2 + j;
        cbuf[j] = make_float2(0.f, 0.f);
        if ((k >= kminA) & (k <= kmaxA))
            cbuf[j] = *(const float2*)(costbase + (size_t)(k - 2) * TT);
    }

    int k0 = 2;
    for (int s = 0; s < NSEG; s++) {
        const bool active = (k0 <= W1) & (k0 + SEG - 1 >= W0);

        // ---- gate + batched halo read (once per segment) ----
        if (active && (w > 0)) {
            if (vprog[w - 1] < s + 1) {
                while (vprog[w - 1] < s + 1) __nanosleep(20);
            }
            __threadfence_block();
            float4 h0 = *(const float4*)&lhalo[k0 - 2];  // broadcast LDS.128
            float4 h1 = *(const float4*)&lhalo[k0 + 2];
            hb[0] = h0.x; hb[1] = h0.y; hb[2] = h0.z; hb[3] = h0.w;
            hb[4] = h1.x; hb[5] = h1.y; hb[6] = h1.z; hb[7] = h1.w;
        }

        // ---- prefetch next segment costs ----
        const int k0n = k0 + SEG;
        if ((k0n <= W1) & (k0n + SEG - 1 >= W0) & (s + 1 < NSEG)) {
            const float* p = costbase + (size_t)(k0n - 2) * TT;
            if ((k0n >= P0) & (k0n + SEG - 1 <= P1)) {
                #pragma unroll
                for (int j = 0; j < SEG; j++)
                    nbuf[j] = *(const float2*)(p + (size_t)j * TT);
            } else {
                #pragma unroll
                for (int j = 0; j < SEG; j++) {
                    int k = k0n + j;
                    nbuf[j] = make_float2(0.f, 0.f);
                    if ((k >= kminA) & (k <= kmaxA))
                        nbuf[j] = *(const float2*)(p + (size_t)j * TT);
                }
            }
        }

        // ---- compute segment (branch-free, memory-free inner loops) ----
        float sh[SEG];
        if (!active) {
            #pragma unroll
            for (int j = 0; j < SEG; j++) sh[j] = BIGV;
        } else if ((k0 >= F0) & (k0 + SEG - 1 <= F1)) {
            // interior fast path
            #pragma unroll
            for (int j = 0; j < SEG; j++) {
                float cur1 = cbuf[j].y + softmin3(v2_0, v1_0, v1_1);
                float cur0 = cbuf[j].x + softmin3(L2, L1, v1_0);
                float nb = __shfl_up_sync(0xffffffffu, cur1, 1);
                nb = (lane == 0) ? hb[j] : nb;     // SEL, no branch
                sh[j] = cur1;
                L2 = L1; L1 = nb;
                v2_0 = v1_0; v2_1 = v1_1;
                v1_0 = cur0; v1_1 = cur1;
                res = cur1;
            }
        } else {
            // edge path (masked with selects; still branch-free per diag)
            #pragma unroll
            for (int j = 0; j < SEG; j++) {
                const int k = k0 + j;
                const int rlo = k - 1 - TT;
                const int rhi = k - 2;
                const bool tv = (k >= kminA) & (k <= kmaxA);

                float sm1 = softmin3(v2_0, v1_0, v1_1);
                float sm0 = softmin3(L2, L1, v1_0);
                int r1 = r0 + 1;
                float cur1 = (tv & (r1 >= rlo) & (r1 <= rhi)) ? cbuf[j].y + sm1 : BIGV;
                float cur0 = (tv & (r0 >= rlo) & (r0 <= rhi)) ? cbuf[j].x + sm0 : BIGV;
                res = tv ? cur1 : res;

                float nb = __shfl_up_sync(0xffffffffu, cur1, 1);
                nb = (lane == 0) ? hb[j] : nb;
                sh[j] = cur1;
                L2 = L1; L1 = nb;
                v2_0 = v1_0; v2_1 = v1_1;
                v1_0 = cur0; v1_1 = cur1;
            }
        }

        // ---- epilogue: batched halo store + progress publish ----
        if (w < 15) {
            if (lane == 31) {
                *(float4*)&myhalo[k0 - 2] = make_float4(sh[0], sh[1], sh[2], sh[3]);
                *(float4*)&myhalo[k0 + 2] = make_float4(sh[4], sh[5], sh[6], sh[7]);
            }
            __threadfence_block();
            if (lane == 0) vprog[w] = s + 1;
        }

        #pragma unroll
        for (int j = 0; j < SEG; j++) cbuf[j] = nbuf[j];
        k0 = k0n;
    }

    // answer = d_{2T}[T]: row 1023 -> thread 511, second row (k = 2048)
    if (t == 511) out[b] = res;
}

extern "C" void kernel_launch(void* const* d_in, const int* in_sizes, int n_in,
                              void* d_out, int out_size) {
    const float* x = (const float*)d_in[0];
    const float* y = (const float*)d_in[1];
    float* out = (float*)d_out;

    cudaFuncSetAttribute(dp_kernel,
                         cudaFuncAttributeMaxDynamicSharedMemorySize, HALO_BYTES);

    dim3 gridA(TT / 64, TT / 64, BB);   // (16, 16, 32)
    cost_kernel<<<gridA, 256>>>(x, y);
    dp_kernel<<<BB, 512, HALO_BYTES>>>(out);
}